// round 1
// baseline (speedup 1.0000x reference)
#include <cuda_runtime.h>
#include <math.h>

#define H      2048
#define E      8
#define HV     (H / 4)      // 512 float4 per row
#define TPW    4            // tokens per warp
#define NWARPS 8
#define TPB    (TPW * NWARPS)  // 32 tokens per block
#define NTHR   256
#define ALPHA  0.01f

// global accumulators: [0..7] = expert counts, [8..15] = sum of softmax probs
__device__ float g_acc[2 * E];

__global__ __launch_bounds__(NTHR)
void moe_gate_kernel(const float* __restrict__ x,
                     const float* __restrict__ w,
                     float* __restrict__ out_idx,   // T*2 floats
                     float* __restrict__ out_wgt,   // T*2 floats
                     int T)
{
    extern __shared__ float smem[];               // E*H floats = 64KB
    float4* w4 = reinterpret_cast<float4*>(smem);
    __shared__ float s_cnt[E];
    __shared__ float s_psum[E];

    const int tid  = threadIdx.x;
    const int warp = tid >> 5;
    const int lane = tid & 31;

    if (tid < E)            s_cnt[tid] = 0.0f;
    else if (tid < 2 * E)   s_psum[tid - E] = 0.0f;

    // stage weight [E,H] into smem as float4, row-major e*HV + idx
    {
        const float4* wg = reinterpret_cast<const float4*>(w);
        #pragma unroll
        for (int i = 0; i < (E * HV) / NTHR; i++)
            w4[tid + i * NTHR] = wg[tid + i * NTHR];
    }
    __syncthreads();

    const int tok0 = blockIdx.x * TPB + warp * TPW;
    const float4* x4 = reinterpret_cast<const float4*>(x);

    float acc[TPW][E];
    #pragma unroll
    for (int t = 0; t < TPW; t++)
        #pragma unroll
        for (int e = 0; e < E; e++)
            acc[t][e] = 0.0f;

    #pragma unroll 2
    for (int it = 0; it < HV / 32; it++) {
        const int idx = it * 32 + lane;
        float4 xv[TPW];
        #pragma unroll
        for (int t = 0; t < TPW; t++)
            xv[t] = x4[(size_t)(tok0 + t) * HV + idx];
        #pragma unroll
        for (int e = 0; e < E; e++) {
            const float4 wv = w4[e * HV + idx];
            #pragma unroll
            for (int t = 0; t < TPW; t++) {
                acc[t][e] = fmaf(xv[t].x, wv.x, acc[t][e]);
                acc[t][e] = fmaf(xv[t].y, wv.y, acc[t][e]);
                acc[t][e] = fmaf(xv[t].z, wv.z, acc[t][e]);
                acc[t][e] = fmaf(xv[t].w, wv.w, acc[t][e]);
            }
        }
    }

    // warp tree-reduce every accumulator (all lanes end with full sums)
    #pragma unroll
    for (int t = 0; t < TPW; t++)
        #pragma unroll
        for (int e = 0; e < E; e++) {
            float v = acc[t][e];
            v += __shfl_xor_sync(0xffffffffu, v, 16);
            v += __shfl_xor_sync(0xffffffffu, v, 8);
            v += __shfl_xor_sync(0xffffffffu, v, 4);
            v += __shfl_xor_sync(0xffffffffu, v, 2);
            v += __shfl_xor_sync(0xffffffffu, v, 1);
            acc[t][e] = v;
        }

    if (lane < TPW) {
        const int tok = tok0 + lane;
        float lg[E];
        #pragma unroll
        for (int e = 0; e < E; e++) lg[e] = acc[lane][e];

        // softmax
        float m = lg[0];
        #pragma unroll
        for (int e = 1; e < E; e++) m = fmaxf(m, lg[e]);
        float p[E];
        float s = 0.0f;
        #pragma unroll
        for (int e = 0; e < E; e++) { p[e] = __expf(lg[e] - m); s += p[e]; }
        const float inv = 1.0f / s;

        // top-2 on logits (same order as scores); ties -> lowest index first
        int i1 = 0; float b1 = lg[0];
        #pragma unroll
        for (int e = 1; e < E; e++)
            if (lg[e] > b1) { b1 = lg[e]; i1 = e; }
        int i2 = -1; float b2 = -INFINITY;
        #pragma unroll
        for (int e = 0; e < E; e++)
            if (e != i1 && lg[e] > b2) { b2 = lg[e]; i2 = e; }

        out_idx[2 * tok]     = (float)i1;
        out_idx[2 * tok + 1] = (float)i2;
        out_wgt[2 * tok]     = p[i1] * inv;
        out_wgt[2 * tok + 1] = p[i2] * inv;

        atomicAdd(&s_cnt[i1], 1.0f);
        atomicAdd(&s_cnt[i2], 1.0f);
        #pragma unroll
        for (int e = 0; e < E; e++)
            atomicAdd(&s_psum[e], p[e] * inv);
    }

    __syncthreads();
    if (tid < E)           atomicAdd(&g_acc[tid], s_cnt[tid]);
    else if (tid < 2 * E)  atomicAdd(&g_acc[tid], s_psum[tid - E]);
}

__global__ void moe_gate_finalize(float* __restrict__ out_aux, int T)
{
    if (threadIdx.x == 0) {
        float aux = 0.0f;
        const float invT  = 1.0f / (float)T;
        const float invTK = 1.0f / ((float)T * 2.0f);
        #pragma unroll
        for (int e = 0; e < E; e++) {
            const float Pi = g_acc[E + e] * invT;
            const float fi = g_acc[e] * invTK * (float)E;
            aux += Pi * fi;
        }
        out_aux[0] = aux * ALPHA;
    }
}

extern "C" void kernel_launch(void* const* d_in, const int* in_sizes, int n_in,
                              void* d_out, int out_size)
{
    const float* x = (const float*)d_in[0];   // [T, H] flattened
    const float* w = (const float*)d_in[1];   // [E, H]
    const int T = in_sizes[0] / H;            // 16384

    float* out = (float*)d_out;
    float* out_idx = out;                     // [T,2]
    float* out_wgt = out + (size_t)T * 2;     // [T,2]
    float* out_aux = out + (size_t)T * 4;     // [1]

    void* accp = nullptr;
    cudaGetSymbolAddress(&accp, g_acc);
    cudaMemsetAsync(accp, 0, 2 * E * sizeof(float));

    const int smem_bytes = E * H * (int)sizeof(float);   // 64KB
    cudaFuncSetAttribute(moe_gate_kernel,
                         cudaFuncAttributeMaxDynamicSharedMemorySize, smem_bytes);

    moe_gate_kernel<<<T / TPB, NTHR, smem_bytes>>>(x, w, out_idx, out_wgt, T);
    moe_gate_finalize<<<1, 32>>>(out_aux, T);
}